// round 11
// baseline (speedup 1.0000x reference)
#include <cuda_runtime.h>
#include <cuda_fp16.h>
#include <cstddef>

#define N_SRC   16384
#define N_TGT   65536
#define KNBR    8
#define CCH     16
#define CSKIP   2
#define SSC     32
#define HID     64
#define MVD     16
#define ROW_MV  (CCH*MVD)      // 256
#define TPB     128
#define TGT_PER_BLOCK 16
#define HA_STRIDE 68
#define SK_STRIDE 36
#define NPREP      512          // prep blocks (must be <= guaranteed wave-1 size)
#define PREP_ROWS  32           // source rows per prep block (512*32 = 16384)

// fp16 transformed sources + weight side-products
__device__ __half g_mvTh[(size_t)N_SRC * ROW_MV]; // mv_src @ Weff[0:16]
__device__ __half g_scTh[(size_t)N_SRC * HID];    // sc_src @ W1a
__device__ __half g_w1bh[SSC * HID];              // W1_s rows 32..63
__device__ __half g_w2p[HID * SSC];               // W2 packed [hc][ch][r]
__device__ float  g_wsk[2 * CCH];                 // Weff rows 16,17
// dependency + reset counters (zero-initialized at module load; self-resetting)
__device__ unsigned g_prep_done;
__device__ unsigned g_fin;

__device__ __forceinline__ float gelu_tanh(float x)
{
    const float c0 = 0.7978845608028654f;
    float u = c0 * fmaf(0.044715f * x, x * x, x);
    float t = tanhf(u);
    return 0.5f * x * (1.0f + t);
}

// pool layout (floats):
//   prep : w1a[0,2048)  we[2048,2304)  xs[2304,3360) (32x33)  rows[3360,4384) (4x256)
//   fused: sHA[0,1088)  sSK[1088,1664)
#define POOL_F 4384

__global__ __launch_bounds__(TPB, 6) void mega_kernel(
    const float* __restrict__ mv_src,  const float* __restrict__ mv_skip,
    const float* __restrict__ sc_src,  const float* __restrict__ sc_skip,
    const float* __restrict__ pos_src, const float* __restrict__ pos_tgt,
    const int*   __restrict__ isrc,
    const float* __restrict__ W1_mv,   const float* __restrict__ W2_mv,
    const float* __restrict__ W1_s,    const float* __restrict__ b1_s,
    const float* __restrict__ W2_s,    const float* __restrict__ b2_s,
    float* __restrict__ out_mv,        float* __restrict__ out_sc)
{
    __shared__ __align__(16) float pool[POOL_F];

    const int tid  = threadIdx.x;
    const int lane = tid & 31;
    const int warp = tid >> 5;

    // ===================== PREP PHASE (blocks 0..NPREP-1) ===================
    if (blockIdx.x < NPREP) {
        float* w1a  = pool;
        float* we   = pool + 2048;
        float* xs   = pool + 2304;      // stride 33
        float* rows = pool + 3360;      // 4 rows x 256
        const int s0 = blockIdx.x * PREP_ROWS;

        // stage W1a (2048 floats, coalesced)
        #pragma unroll
        for (int i = 0; i < 16; i++) w1a[tid + 128 * i] = __ldg(W1_s + tid + 128 * i);
        // stage sc rows into xs (stride-33 pad)
        #pragma unroll
        for (int it = 0; it < 8; it++) {
            const int idx = tid + 128 * it;          // 0..1023
            const int r = idx >> 5, j = idx & 31;
            xs[r * 33 + j] = __ldg(sc_src + (size_t)(s0 + r) * SSC + j);
        }
        // Weff[cp][c] for cp<16 (2 entries/thread; few distinct addrs -> L1 broadcast)
        #pragma unroll
        for (int e = 0; e < 2; e++) {
            const int idx = tid * 2 + e;
            const int cp = idx >> 4, c = idx & 15;
            float acc = 0.f;
            #pragma unroll
            for (int h = 0; h < HID; h++)
                acc = fmaf(__ldg(W1_mv + cp * HID + h), __ldg(W2_mv + h * CCH + c), acc);
            we[idx] = acc;
        }
        // block 0: weight side-products
        if (blockIdx.x == 0) {
            #pragma unroll
            for (int i = 0; i < 16; i++) {
                const int idx = tid + 128 * i;       // 0..2047
                g_w1bh[idx] = __float2half_rn(__ldg(W1_s + SSC * HID + idx));
                const int hc = idx >> 8, ch = (idx >> 3) & 31, r = idx & 7;
                g_w2p[idx] = __float2half_rn(__ldg(W2_s + (hc * 8 + r) * SSC + ch));
            }
            if (tid < 32) {
                const int cp = 16 + (tid >> 4), c = tid & 15;
                float acc = 0.f;
                #pragma unroll
                for (int h = 0; h < HID; h++)
                    acc = fmaf(__ldg(W1_mv + cp * HID + h), __ldg(W2_mv + h * CCH + c), acc);
                g_wsk[tid] = acc;
            }
        }
        __syncthreads();

        // mvT fp16: 8 chunks of 4 rows
        const int mrow = tid >> 5;           // warp -> row in chunk
        const int q    = tid & 31;
        const int c    = q >> 1;
        const int i0   = (q & 1) * 8;
        for (int ch = 0; ch < 8; ch++) {
            // stage 4 rows (1024 floats = 256 float4)
            {
                const float4* src = (const float4*)(mv_src + (size_t)(s0 + ch * 4) * 256);
                float4* dst = (float4*)rows;
                dst[tid]       = __ldg(src + tid);
                dst[tid + 128] = __ldg(src + tid + 128);
            }
            __syncthreads();
            {
                const float* row = rows + mrow * 256;
                float acc[8];
                #pragma unroll
                for (int di = 0; di < 8; di++) acc[di] = 0.f;
                #pragma unroll
                for (int cp = 0; cp < 16; cp++) {
                    const float wv = we[cp * 16 + c];
                    const float* rp = row + cp * 16 + i0;
                    #pragma unroll
                    for (int di = 0; di < 8; di++)
                        acc[di] = fmaf(rp[di], wv, acc[di]);
                }
                __half2 h2[4];
                #pragma unroll
                for (int p = 0; p < 4; p++)
                    h2[p] = __floats2half2_rn(acc[2 * p], acc[2 * p + 1]);
                *(uint4*)(g_mvTh + (size_t)(s0 + ch * 4 + mrow) * 256 + c * 16 + i0) =
                    *(const uint4*)h2;
            }
            __syncthreads();
        }

        // scT fp16: warp w handles h [16w,16w+16) for all 32 rows; thread row = lane
        {
            const int hb = warp * 16;
            const float* xr = xs + lane * 33;
            float acc[16];
            {
                #pragma unroll
                for (int dh = 0; dh < 16; dh++) acc[dh] = 0.f;
                #pragma unroll
                for (int j = 0; j < 32; j++) {
                    const float x = xr[j];
                    const float* wr = w1a + j * HID + hb;   // warp-uniform -> broadcast
                    #pragma unroll
                    for (int dh = 0; dh < 16; dh++)
                        acc[dh] = fmaf(x, wr[dh], acc[dh]);
                }
            }
            __half2 h2[8];
            #pragma unroll
            for (int p = 0; p < 8; p++)
                h2[p] = __floats2half2_rn(acc[2 * p], acc[2 * p + 1]);
            uint4* dst = (uint4*)(g_scTh + (size_t)(s0 + lane) * HID + hb);
            dst[0] = ((const uint4*)h2)[0];
            dst[1] = ((const uint4*)h2)[1];
        }

        __syncthreads();
        __threadfence();
        if (tid == 0) atomicAdd(&g_prep_done, 1u);
    }

    // ===================== WAIT FOR PREP =====================================
    if (tid == 0) {
        while (*(volatile unsigned*)&g_prep_done < NPREP) __nanosleep(64);
    }
    __syncthreads();

    // ===================== FUSED PHASE (all 4096 blocks) =====================
    float* sHA = pool;                              // 16 x 68
    float* sSK = pool + TGT_PER_BLOCK * HA_STRIDE;  // 16 x 36
    const int tbase = blockIdx.x * TGT_PER_BLOCK;
    const int r0 = warp * 4;

    const int cch = lane >> 1;
    const float w16 = g_wsk[cch];
    const float w17 = g_wsk[16 + cch];

    // ---- Phase 1: IDW gather of fp16 transformed sources ----
    #pragma unroll
    for (int u = 0; u < 4; u++) {
        const int tl = r0 + u;
        const int t  = tbase + tl;

        float wk = 0.f;
        int   sk = 0;
        if (lane < KNBR) {
            sk = isrc[t * KNBR + lane];
            float dx = pos_src[sk * 3 + 0] - pos_tgt[t * 3 + 0];
            float dy = pos_src[sk * 3 + 1] - pos_tgt[t * 3 + 1];
            float dz = pos_src[sk * 3 + 2] - pos_tgt[t * 3 + 2];
            float d2 = fmaf(dx, dx, fmaf(dy, dy, dz * dz));
            d2 = fmaxf(d2, 1e-16f);
            wk = 1.0f / d2;
        }
        float den = wk;
        #pragma unroll
        for (int o = 16; o; o >>= 1) den += __shfl_xor_sync(0xffffffffu, den, o);
        const float invd = 1.0f / den;

        float acc[8];
        #pragma unroll
        for (int j = 0; j < 8; j++) acc[j] = 0.f;
        float h0 = 0.f, h1 = 0.f;

        #pragma unroll
        for (int k = 0; k < KNBR; k++) {
            const float w = __shfl_sync(0xffffffffu, wk, k);
            const int   s = __shfl_sync(0xffffffffu, sk, k);
            uint4 v = __ldg((const uint4*)(g_mvTh + (size_t)s * ROW_MV) + lane);
            const __half2* hv = (const __half2*)&v;
            float2 f0 = __half22float2(hv[0]);
            float2 f1 = __half22float2(hv[1]);
            float2 f2 = __half22float2(hv[2]);
            float2 f3 = __half22float2(hv[3]);
            acc[0] = fmaf(w, f0.x, acc[0]); acc[1] = fmaf(w, f0.y, acc[1]);
            acc[2] = fmaf(w, f1.x, acc[2]); acc[3] = fmaf(w, f1.y, acc[3]);
            acc[4] = fmaf(w, f2.x, acc[4]); acc[5] = fmaf(w, f2.y, acc[5]);
            acc[6] = fmaf(w, f3.x, acc[6]); acc[7] = fmaf(w, f3.y, acc[7]);
            __half2 sv = __ldg((const __half2*)(g_scTh + (size_t)s * HID) + lane);
            float2 sf = __half22float2(sv);
            h0 = fmaf(w, sf.x, h0); h1 = fmaf(w, sf.y, h1);
        }

        const int ib = (lane & 1) * 8;
        float4 s0a = __ldg((const float4*)(mv_skip + (size_t)t * 32 + ib));
        float4 s0b = __ldg((const float4*)(mv_skip + (size_t)t * 32 + ib + 4));
        float4 s1a = __ldg((const float4*)(mv_skip + (size_t)t * 32 + 16 + ib));
        float4 s1b = __ldg((const float4*)(mv_skip + (size_t)t * 32 + 16 + ib + 4));

        float4 o0, o1;
        o0.x = fmaf(acc[0], invd, fmaf(s0a.x, w16, s1a.x * w17));
        o0.y = fmaf(acc[1], invd, fmaf(s0a.y, w16, s1a.y * w17));
        o0.z = fmaf(acc[2], invd, fmaf(s0a.z, w16, s1a.z * w17));
        o0.w = fmaf(acc[3], invd, fmaf(s0a.w, w16, s1a.w * w17));
        o1.x = fmaf(acc[4], invd, fmaf(s0b.x, w16, s1b.x * w17));
        o1.y = fmaf(acc[5], invd, fmaf(s0b.y, w16, s1b.y * w17));
        o1.z = fmaf(acc[6], invd, fmaf(s0b.z, w16, s1b.z * w17));
        o1.w = fmaf(acc[7], invd, fmaf(s0b.w, w16, s1b.w * w17));

        float4* dst = (float4*)(out_mv + (size_t)t * ROW_MV + 8 * lane);
        dst[0] = o0;
        dst[1] = o1;

        *(float2*)(sHA + tl * HA_STRIDE + 2 * lane) = make_float2(h0 * invd, h1 * invd);
        sSK[tl * SK_STRIDE + lane] = sc_skip[(size_t)t * SSC + lane];
    }
    __syncwarp();

    // ---- Phase 3a: hidden = gelu(interp_part + skip@W1b + b1) ----
    {
        float2 bb = __ldg((const float2*)(b1_s + 2 * lane));
        float2 i0 = *(const float2*)(sHA + (r0 + 0) * HA_STRIDE + 2 * lane);
        float2 i1 = *(const float2*)(sHA + (r0 + 1) * HA_STRIDE + 2 * lane);
        float2 i2 = *(const float2*)(sHA + (r0 + 2) * HA_STRIDE + 2 * lane);
        float2 i3 = *(const float2*)(sHA + (r0 + 3) * HA_STRIDE + 2 * lane);
        float a0x = bb.x + i0.x, a0y = bb.y + i0.y;
        float a1x = bb.x + i1.x, a1y = bb.y + i1.y;
        float a2x = bb.x + i2.x, a2y = bb.y + i2.y;
        float a3x = bb.x + i3.x, a3y = bb.y + i3.y;
        const float* x0 = sSK + (r0 + 0) * SK_STRIDE;
        const float* x1 = sSK + (r0 + 1) * SK_STRIDE;
        const float* x2 = sSK + (r0 + 2) * SK_STRIDE;
        const float* x3 = sSK + (r0 + 3) * SK_STRIDE;
        #pragma unroll
        for (int jc = 0; jc < 8; jc++) {
            float4 v0 = *(const float4*)(x0 + 4 * jc);
            float4 v1 = *(const float4*)(x1 + 4 * jc);
            float4 v2 = *(const float4*)(x2 + 4 * jc);
            float4 v3 = *(const float4*)(x3 + 4 * jc);
            #pragma unroll
            for (int r = 0; r < 4; r++) {
                const int j = 4 * jc + r;
                __half2 wh = __ldg((const __half2*)(g_w1bh + j * HID + 2 * lane));
                float2 wv = __half22float2(wh);
                const float e0 = (r == 0) ? v0.x : (r == 1) ? v0.y : (r == 2) ? v0.z : v0.w;
                const float e1 = (r == 0) ? v1.x : (r == 1) ? v1.y : (r == 2) ? v1.z : v1.w;
                const float e2 = (r == 0) ? v2.x : (r == 1) ? v2.y : (r == 2) ? v2.z : v2.w;
                const float e3 = (r == 0) ? v3.x : (r == 1) ? v3.y : (r == 2) ? v3.z : v3.w;
                a0x = fmaf(e0, wv.x, a0x); a0y = fmaf(e0, wv.y, a0y);
                a1x = fmaf(e1, wv.x, a1x); a1y = fmaf(e1, wv.y, a1y);
                a2x = fmaf(e2, wv.x, a2x); a2y = fmaf(e2, wv.y, a2y);
                a3x = fmaf(e3, wv.x, a3x); a3y = fmaf(e3, wv.y, a3y);
            }
        }
        *(float2*)(sHA + (r0 + 0) * HA_STRIDE + 2 * lane) = make_float2(gelu_tanh(a0x), gelu_tanh(a0y));
        *(float2*)(sHA + (r0 + 1) * HA_STRIDE + 2 * lane) = make_float2(gelu_tanh(a1x), gelu_tanh(a1y));
        *(float2*)(sHA + (r0 + 2) * HA_STRIDE + 2 * lane) = make_float2(gelu_tanh(a2x), gelu_tanh(a2y));
        *(float2*)(sHA + (r0 + 3) * HA_STRIDE + 2 * lane) = make_float2(gelu_tanh(a3x), gelu_tanh(a3y));
    }
    __syncwarp();

    // ---- Phase 3b: scalar output (lane = channel, packed fp16 W2) ----
    {
        const float bb = __ldg(b2_s + lane);
        float a0 = bb, a1 = bb, a2 = bb, a3 = bb;
        const float* h0 = sHA + (r0 + 0) * HA_STRIDE;
        const float* h1 = sHA + (r0 + 1) * HA_STRIDE;
        const float* h2 = sHA + (r0 + 2) * HA_STRIDE;
        const float* h3 = sHA + (r0 + 3) * HA_STRIDE;
        #pragma unroll
        for (int hc = 0; hc < 8; hc++) {
            uint4 wv = __ldg((const uint4*)(g_w2p + hc * 256 + lane * 8));
            const __half2* wh = (const __half2*)&wv;
            float2 wf0 = __half22float2(wh[0]);
            float2 wf1 = __half22float2(wh[1]);
            float2 wf2 = __half22float2(wh[2]);
            float2 wf3 = __half22float2(wh[3]);
            float4 va0 = *(const float4*)(h0 + 8 * hc);
            float4 vb0 = *(const float4*)(h0 + 8 * hc + 4);
            float4 va1 = *(const float4*)(h1 + 8 * hc);
            float4 vb1 = *(const float4*)(h1 + 8 * hc + 4);
            float4 va2 = *(const float4*)(h2 + 8 * hc);
            float4 vb2 = *(const float4*)(h2 + 8 * hc + 4);
            float4 va3 = *(const float4*)(h3 + 8 * hc);
            float4 vb3 = *(const float4*)(h3 + 8 * hc + 4);
            a0 = fmaf(va0.x, wf0.x, a0); a0 = fmaf(va0.y, wf0.y, a0);
            a0 = fmaf(va0.z, wf1.x, a0); a0 = fmaf(va0.w, wf1.y, a0);
            a0 = fmaf(vb0.x, wf2.x, a0); a0 = fmaf(vb0.y, wf2.y, a0);
            a0 = fmaf(vb0.z, wf3.x, a0); a0 = fmaf(vb0.w, wf3.y, a0);
            a1 = fmaf(va1.x, wf0.x, a1); a1 = fmaf(va1.y, wf0.y, a1);
            a1 = fmaf(va1.z, wf1.x, a1); a1 = fmaf(va1.w, wf1.y, a1);
            a1 = fmaf(vb1.x, wf2.x, a1); a1 = fmaf(vb1.y, wf2.y, a1);
            a1 = fmaf(vb1.z, wf3.x, a1); a1 = fmaf(vb1.w, wf3.y, a1);
            a2 = fmaf(va2.x, wf0.x, a2); a2 = fmaf(va2.y, wf0.y, a2);
            a2 = fmaf(va2.z, wf1.x, a2); a2 = fmaf(va2.w, wf1.y, a2);
            a2 = fmaf(vb2.x, wf2.x, a2); a2 = fmaf(vb2.y, wf2.y, a2);
            a2 = fmaf(vb2.z, wf3.x, a2); a2 = fmaf(vb2.w, wf3.y, a2);
            a3 = fmaf(va3.x, wf0.x, a3); a3 = fmaf(va3.y, wf0.y, a3);
            a3 = fmaf(va3.z, wf1.x, a3); a3 = fmaf(va3.w, wf1.y, a3);
            a3 = fmaf(vb3.x, wf2.x, a3); a3 = fmaf(vb3.y, wf2.y, a3);
            a3 = fmaf(vb3.z, wf3.x, a3); a3 = fmaf(vb3.w, wf3.y, a3);
        }
        out_sc[(size_t)(tbase + r0 + 0) * SSC + lane] = a0;
        out_sc[(size_t)(tbase + r0 + 1) * SSC + lane] = a1;
        out_sc[(size_t)(tbase + r0 + 2) * SSC + lane] = a2;
        out_sc[(size_t)(tbase + r0 + 3) * SSC + lane] = a3;
    }

    // ===================== COUNTER RESET (idempotence across replays) ========
    __syncthreads();
    if (tid == 0) {
        __threadfence();
        unsigned d = atomicAdd(&g_fin, 1u);
        if (d == gridDim.x - 1) {
            g_prep_done = 0;
            g_fin = 0;
            __threadfence();
        }
    }
}

// ---------------------------------------------------------------------------
extern "C" void kernel_launch(void* const* d_in, const int* in_sizes, int n_in,
                              void* d_out, int out_size)
{
    const float* mv_src   = (const float*)d_in[0];
    const float* mv_skip  = (const float*)d_in[1];
    const float* sc_src   = (const float*)d_in[2];
    const float* sc_skip  = (const float*)d_in[3];
    const float* pos_src  = (const float*)d_in[4];
    const float* pos_tgt  = (const float*)d_in[5];
    const int*   isrc     = (const int*)d_in[6];
    const float* W1_mv    = (const float*)d_in[8];
    const float* W2_mv    = (const float*)d_in[9];
    const float* W1_s     = (const float*)d_in[10];
    const float* b1_s     = (const float*)d_in[11];
    const float* W2_s     = (const float*)d_in[12];
    const float* b2_s     = (const float*)d_in[13];

    float* out_mv = (float*)d_out;
    float* out_sc = out_mv + (size_t)N_TGT * CCH * MVD;

    mega_kernel<<<N_TGT / TGT_PER_BLOCK, TPB>>>(
        mv_src, mv_skip, sc_src, sc_skip, pos_src, pos_tgt, isrc,
        W1_mv, W2_mv, W1_s, b1_s, W2_s, b2_s, out_mv, out_sc);
}

// round 12
// speedup vs baseline: 1.0510x; 1.0510x over previous
#include <cuda_runtime.h>
#include <cuda_fp16.h>
#include <cstddef>

#define N_SRC   16384
#define N_TGT   65536
#define KNBR    8
#define CCH     16
#define CSKIP   2
#define SSC     32
#define HID     64
#define MVD     16
#define ROW_MV  (CCH*MVD)      // 256
#define TPB     128
#define TGT_PER_BLOCK 16
#define HA_STRIDE 68
#define SK_STRIDE 36
#define PREP_ROWS 16           // source rows per block (1024 blocks)

__device__ __half g_mvTh[(size_t)N_SRC * ROW_MV]; // mv_src @ Weff[0:16]  (8 MB fp16)
__device__ __half g_scTh[(size_t)N_SRC * HID];    // sc_src @ W1a         (2 MB fp16)
__device__ __half g_w1bh[SSC * HID];              // W1_s rows 32..63 fp16
__device__ __half g_w2p[HID * SSC];               // W2 packed: [hc][ch][r] fp16
__device__ float  g_wsk[2 * CCH];                 // Weff rows 16,17

__device__ __forceinline__ float gelu_tanh(float x)
{
    const float c0 = 0.7978845608028654f;
    float u = c0 * fmaf(0.044715f * x, x * x, x);
    float t = tanhf(u);
    return 0.5f * x * (1.0f + t);
}

// ---------------------------------------------------------------------------
// Prep: 1024 blocks x 256 thr, 16 rows each. Minimal smem (~11.2 KB) so the
// whole grid fits in ONE wave (8 blocks/SM); latency ~= one block.
// ---------------------------------------------------------------------------
__global__ __launch_bounds__(256) void prep_all(
    const float* __restrict__ mv_src, const float* __restrict__ sc_src,
    const float* __restrict__ W1_mv,  const float* __restrict__ W2_mv,
    const float* __restrict__ W1_s,   const float* __restrict__ W2_s)
{
    __shared__ __align__(16) float rows[8 * 256];           // 8 KB (chunk of 8 rows)
    __shared__ __align__(16) float we[CCH * CCH];           // 1 KB
    __shared__ __align__(16) float xs[PREP_ROWS * 33];      // 2.1 KB

    const int tid = threadIdx.x;
    const int s0  = blockIdx.x * PREP_ROWS;

    // Weff[cp][c] for cp<16: one entry per thread, warp-uniform-ish __ldg dots
    {
        const int cp = tid >> 4, c = tid & 15;
        float acc = 0.f;
        #pragma unroll
        for (int h = 0; h < HID; h++)
            acc = fmaf(__ldg(W1_mv + cp * HID + h), __ldg(W2_mv + h * CCH + c), acc);
        we[tid] = acc;
    }
    // stage sc rows (512 floats)
    {
        int idx = tid;
        xs[(idx >> 5) * 33 + (idx & 31)] = __ldg(sc_src + (size_t)s0 * SSC + idx);
        idx = tid + 256;
        xs[(idx >> 5) * 33 + (idx & 31)] = __ldg(sc_src + (size_t)s0 * SSC + idx);
    }
    // block 0: weight side-products
    if (blockIdx.x == 0) {
        #pragma unroll
        for (int i = 0; i < 8; i++) {
            const int idx = tid + 256 * i;               // 0..2047
            g_w1bh[idx] = __float2half_rn(__ldg(W1_s + SSC * HID + idx));
            const int hc = idx >> 8, ch = (idx >> 3) & 31, r = idx & 7;
            g_w2p[idx] = __float2half_rn(__ldg(W2_s + (hc * 8 + r) * SSC + ch));
        }
        if (tid < 32) {
            const int cp = 16 + (tid >> 4), c = tid & 15;
            float acc = 0.f;
            #pragma unroll
            for (int h = 0; h < HID; h++)
                acc = fmaf(__ldg(W1_mv + cp * HID + h), __ldg(W2_mv + h * CCH + c), acc);
            g_wsk[tid] = acc;
        }
    }
    __syncthreads();

    // ---- mvT fp16: 2 chunks of 8 rows (warp per row within chunk) ----
    const int mrow = tid >> 5;           // 0..7
    const int q    = tid & 31;
    const int c    = q >> 1;             // output channel
    const int i0   = (q & 1) * 8;        // blade offset
    #pragma unroll
    for (int ch = 0; ch < 2; ch++) {
        // stage 8 rows = 2048 floats = 512 float4
        {
            const float4* src = (const float4*)(mv_src + (size_t)(s0 + ch * 8) * 256);
            float4* dst = (float4*)rows;
            dst[tid]       = __ldg(src + tid);
            dst[tid + 256] = __ldg(src + tid + 256);
        }
        __syncthreads();
        {
            const float* row = rows + mrow * 256;
            float acc[8];
            #pragma unroll
            for (int di = 0; di < 8; di++) acc[di] = 0.f;
            #pragma unroll
            for (int cp = 0; cp < 16; cp++) {
                const float wv = we[cp * 16 + c];
                const float* rp = row + cp * 16 + i0;
                #pragma unroll
                for (int di = 0; di < 8; di++)
                    acc[di] = fmaf(rp[di], wv, acc[di]);
            }
            __half2 h2[4];
            #pragma unroll
            for (int p = 0; p < 4; p++)
                h2[p] = __floats2half2_rn(acc[2 * p], acc[2 * p + 1]);
            *(uint4*)(g_mvTh + (size_t)(s0 + ch * 8 + mrow) * 256 + c * 16 + i0) =
                *(const uint4*)h2;
        }
        __syncthreads();
    }

    // ---- scT fp16: 2 passes; thread -> (row, h pair); w1a direct __ldg ----
    {
        const int h0 = (tid & 31) * 2;
        #pragma unroll
        for (int it = 0; it < 2; it++) {
            const int r = it * 8 + (tid >> 5);
            const float* xr = xs + r * 33;
            float a0 = 0.f, a1 = 0.f;
            #pragma unroll
            for (int j = 0; j < 32; j++) {
                const float x = xr[j];
                float2 wv = __ldg((const float2*)(W1_s + j * HID + h0));
                a0 = fmaf(x, wv.x, a0);
                a1 = fmaf(x, wv.y, a1);
            }
            *(__half2*)(g_scTh + (size_t)(s0 + r) * HID + h0) =
                __floats2half2_rn(a0, a1);
        }
    }
}

// ---------------------------------------------------------------------------
// Warp-private pipeline (unchanged from R10 — 59.4us measured)
// ---------------------------------------------------------------------------
__global__ __launch_bounds__(TPB, 6) void fused_kernel(
    const float* __restrict__ mv_skip, const float* __restrict__ sc_skip,
    const float* __restrict__ pos_src, const float* __restrict__ pos_tgt,
    const int*   __restrict__ isrc,
    const float* __restrict__ b1_s,    const float* __restrict__ b2_s,
    float* __restrict__ out_mv,        float* __restrict__ out_sc)
{
    __shared__ __align__(16) float sHA[TGT_PER_BLOCK * HA_STRIDE];
    __shared__ __align__(16) float sSK[TGT_PER_BLOCK * SK_STRIDE];

    const int tid  = threadIdx.x;
    const int lane = tid & 31;
    const int warp = tid >> 5;
    const int tbase = blockIdx.x * TGT_PER_BLOCK;
    const int r0 = warp * 4;

    const int cch = lane >> 1;
    const float w16 = __ldg(g_wsk + cch);
    const float w17 = __ldg(g_wsk + 16 + cch);

    // ---------------- Phase 1: IDW gather of fp16 transformed sources -------
    #pragma unroll
    for (int u = 0; u < 4; u++) {
        const int tl = r0 + u;
        const int t  = tbase + tl;

        float wk = 0.f;
        int   sk = 0;
        if (lane < KNBR) {
            sk = isrc[t * KNBR + lane];
            float dx = pos_src[sk * 3 + 0] - pos_tgt[t * 3 + 0];
            float dy = pos_src[sk * 3 + 1] - pos_tgt[t * 3 + 1];
            float dz = pos_src[sk * 3 + 2] - pos_tgt[t * 3 + 2];
            float d2 = fmaf(dx, dx, fmaf(dy, dy, dz * dz));
            d2 = fmaxf(d2, 1e-16f);
            wk = 1.0f / d2;
        }
        float den = wk;
        #pragma unroll
        for (int o = 16; o; o >>= 1) den += __shfl_xor_sync(0xffffffffu, den, o);
        const float invd = 1.0f / den;

        float acc[8];
        #pragma unroll
        for (int j = 0; j < 8; j++) acc[j] = 0.f;
        float h0 = 0.f, h1 = 0.f;

        #pragma unroll
        for (int k = 0; k < KNBR; k++) {
            const float w = __shfl_sync(0xffffffffu, wk, k);
            const int   s = __shfl_sync(0xffffffffu, sk, k);
            uint4 v = __ldg((const uint4*)(g_mvTh + (size_t)s * ROW_MV) + lane);
            const __half2* hv = (const __half2*)&v;
            float2 f0 = __half22float2(hv[0]);
            float2 f1 = __half22float2(hv[1]);
            float2 f2 = __half22float2(hv[2]);
            float2 f3 = __half22float2(hv[3]);
            acc[0] = fmaf(w, f0.x, acc[0]); acc[1] = fmaf(w, f0.y, acc[1]);
            acc[2] = fmaf(w, f1.x, acc[2]); acc[3] = fmaf(w, f1.y, acc[3]);
            acc[4] = fmaf(w, f2.x, acc[4]); acc[5] = fmaf(w, f2.y, acc[5]);
            acc[6] = fmaf(w, f3.x, acc[6]); acc[7] = fmaf(w, f3.y, acc[7]);
            __half2 sv = __ldg((const __half2*)(g_scTh + (size_t)s * HID) + lane);
            float2 sf = __half22float2(sv);
            h0 = fmaf(w, sf.x, h0); h1 = fmaf(w, sf.y, h1);
        }

        const int ib = (lane & 1) * 8;
        float4 s0a = __ldg((const float4*)(mv_skip + (size_t)t * 32 + ib));
        float4 s0b = __ldg((const float4*)(mv_skip + (size_t)t * 32 + ib + 4));
        float4 s1a = __ldg((const float4*)(mv_skip + (size_t)t * 32 + 16 + ib));
        float4 s1b = __ldg((const float4*)(mv_skip + (size_t)t * 32 + 16 + ib + 4));

        float4 o0, o1;
        o0.x = fmaf(acc[0], invd, fmaf(s0a.x, w16, s1a.x * w17));
        o0.y = fmaf(acc[1], invd, fmaf(s0a.y, w16, s1a.y * w17));
        o0.z = fmaf(acc[2], invd, fmaf(s0a.z, w16, s1a.z * w17));
        o0.w = fmaf(acc[3], invd, fmaf(s0a.w, w16, s1a.w * w17));
        o1.x = fmaf(acc[4], invd, fmaf(s0b.x, w16, s1b.x * w17));
        o1.y = fmaf(acc[5], invd, fmaf(s0b.y, w16, s1b.y * w17));
        o1.z = fmaf(acc[6], invd, fmaf(s0b.z, w16, s1b.z * w17));
        o1.w = fmaf(acc[7], invd, fmaf(s0b.w, w16, s1b.w * w17));

        float4* dst = (float4*)(out_mv + (size_t)t * ROW_MV + 8 * lane);
        dst[0] = o0;
        dst[1] = o1;

        *(float2*)(sHA + tl * HA_STRIDE + 2 * lane) = make_float2(h0 * invd, h1 * invd);
        sSK[tl * SK_STRIDE + lane] = sc_skip[(size_t)t * SSC + lane];
    }
    __syncwarp();

    // ---------------- Phase 3a: hidden = gelu(interp_part + skip@W1b + b1) --
    {
        float2 bb = __ldg((const float2*)(b1_s + 2 * lane));
        float2 i0 = *(const float2*)(sHA + (r0 + 0) * HA_STRIDE + 2 * lane);
        float2 i1 = *(const float2*)(sHA + (r0 + 1) * HA_STRIDE + 2 * lane);
        float2 i2 = *(const float2*)(sHA + (r0 + 2) * HA_STRIDE + 2 * lane);
        float2 i3 = *(const float2*)(sHA + (r0 + 3) * HA_STRIDE + 2 * lane);
        float a0x = bb.x + i0.x, a0y = bb.y + i0.y;
        float a1x = bb.x + i1.x, a1y = bb.y + i1.y;
        float a2x = bb.x + i2.x, a2y = bb.y + i2.y;
        float a3x = bb.x + i3.x, a3y = bb.y + i3.y;
        const float* x0 = sSK + (r0 + 0) * SK_STRIDE;
        const float* x1 = sSK + (r0 + 1) * SK_STRIDE;
        const float* x2 = sSK + (r0 + 2) * SK_STRIDE;
        const float* x3 = sSK + (r0 + 3) * SK_STRIDE;
        #pragma unroll
        for (int jc = 0; jc < 8; jc++) {
            float4 v0 = *(const float4*)(x0 + 4 * jc);
            float4 v1 = *(const float4*)(x1 + 4 * jc);
            float4 v2 = *(const float4*)(x2 + 4 * jc);
            float4 v3 = *(const float4*)(x3 + 4 * jc);
            #pragma unroll
            for (int r = 0; r < 4; r++) {
                const int j = 4 * jc + r;
                __half2 wh = __ldg((const __half2*)(g_w1bh + j * HID + 2 * lane));
                float2 wv = __half22float2(wh);
                const float e0 = (r == 0) ? v0.x : (r == 1) ? v0.y : (r == 2) ? v0.z : v0.w;
                const float e1 = (r == 0) ? v1.x : (r == 1) ? v1.y : (r == 2) ? v1.z : v1.w;
                const float e2 = (r == 0) ? v2.x : (r == 1) ? v2.y : (r == 2) ? v2.z : v2.w;
                const float e3 = (r == 0) ? v3.x : (r == 1) ? v3.y : (r == 2) ? v3.z : v3.w;
                a0x = fmaf(e0, wv.x, a0x); a0y = fmaf(e0, wv.y, a0y);
                a1x = fmaf(e1, wv.x, a1x); a1y = fmaf(e1, wv.y, a1y);
                a2x = fmaf(e2, wv.x, a2x); a2y = fmaf(e2, wv.y, a2y);
                a3x = fmaf(e3, wv.x, a3x); a3y = fmaf(e3, wv.y, a3y);
            }
        }
        *(float2*)(sHA + (r0 + 0) * HA_STRIDE + 2 * lane) = make_float2(gelu_tanh(a0x), gelu_tanh(a0y));
        *(float2*)(sHA + (r0 + 1) * HA_STRIDE + 2 * lane) = make_float2(gelu_tanh(a1x), gelu_tanh(a1y));
        *(float2*)(sHA + (r0 + 2) * HA_STRIDE + 2 * lane) = make_float2(gelu_tanh(a2x), gelu_tanh(a2y));
        *(float2*)(sHA + (r0 + 3) * HA_STRIDE + 2 * lane) = make_float2(gelu_tanh(a3x), gelu_tanh(a3y));
    }
    __syncwarp();

    // ---------------- Phase 3b: scalar output (lane = channel, packed fp16 W2)
    {
        const float bb = __ldg(b2_s + lane);
        float a0 = bb, a1 = bb, a2 = bb, a3 = bb;
        const float* h0 = sHA + (r0 + 0) * HA_STRIDE;
        const float* h1 = sHA + (r0 + 1) * HA_STRIDE;
        const float* h2 = sHA + (r0 + 2) * HA_STRIDE;
        const float* h3 = sHA + (r0 + 3) * HA_STRIDE;
        #pragma unroll
        for (int hc = 0; hc < 8; hc++) {
            uint4 wv = __ldg((const uint4*)(g_w2p + hc * 256 + lane * 8));
            const __half2* wh = (const __half2*)&wv;
            float2 wf0 = __half22float2(wh[0]);
            float2 wf1 = __half22float2(wh[1]);
            float2 wf2 = __half22float2(wh[2]);
            float2 wf3 = __half22float2(wh[3]);
            float4 va0 = *(const float4*)(h0 + 8 * hc);
            float4 vb0 = *(const float4*)(h0 + 8 * hc + 4);
            float4 va1 = *(const float4*)(h1 + 8 * hc);
            float4 vb1 = *(const float4*)(h1 + 8 * hc + 4);
            float4 va2 = *(const float4*)(h2 + 8 * hc);
            float4 vb2 = *(const float4*)(h2 + 8 * hc + 4);
            float4 va3 = *(const float4*)(h3 + 8 * hc);
            float4 vb3 = *(const float4*)(h3 + 8 * hc + 4);
            a0 = fmaf(va0.x, wf0.x, a0); a0 = fmaf(va0.y, wf0.y, a0);
            a0 = fmaf(va0.z, wf1.x, a0); a0 = fmaf(va0.w, wf1.y, a0);
            a0 = fmaf(vb0.x, wf2.x, a0); a0 = fmaf(vb0.y, wf2.y, a0);
            a0 = fmaf(vb0.z, wf3.x, a0); a0 = fmaf(vb0.w, wf3.y, a0);
            a1 = fmaf(va1.x, wf0.x, a1); a1 = fmaf(va1.y, wf0.y, a1);
            a1 = fmaf(va1.z, wf1.x, a1); a1 = fmaf(va1.w, wf1.y, a1);
            a1 = fmaf(vb1.x, wf2.x, a1); a1 = fmaf(vb1.y, wf2.y, a1);
            a1 = fmaf(vb1.z, wf3.x, a1); a1 = fmaf(vb1.w, wf3.y, a1);
            a2 = fmaf(va2.x, wf0.x, a2); a2 = fmaf(va2.y, wf0.y, a2);
            a2 = fmaf(va2.z, wf1.x, a2); a2 = fmaf(va2.w, wf1.y, a2);
            a2 = fmaf(vb2.x, wf2.x, a2); a2 = fmaf(vb2.y, wf2.y, a2);
            a2 = fmaf(vb2.z, wf3.x, a2); a2 = fmaf(vb2.w, wf3.y, a2);
            a3 = fmaf(va3.x, wf0.x, a3); a3 = fmaf(va3.y, wf0.y, a3);
            a3 = fmaf(va3.z, wf1.x, a3); a3 = fmaf(va3.w, wf1.y, a3);
            a3 = fmaf(vb3.x, wf2.x, a3); a3 = fmaf(vb3.y, wf2.y, a3);
            a3 = fmaf(vb3.z, wf3.x, a3); a3 = fmaf(vb3.w, wf3.y, a3);
        }
        out_sc[(size_t)(tbase + r0 + 0) * SSC + lane] = a0;
        out_sc[(size_t)(tbase + r0 + 1) * SSC + lane] = a1;
        out_sc[(size_t)(tbase + r0 + 2) * SSC + lane] = a2;
        out_sc[(size_t)(tbase + r0 + 3) * SSC + lane] = a3;
    }
}

// ---------------------------------------------------------------------------
extern "C" void kernel_launch(void* const* d_in, const int* in_sizes, int n_in,
                              void* d_out, int out_size)
{
    const float* mv_src   = (const float*)d_in[0];
    const float* mv_skip  = (const float*)d_in[1];
    const float* sc_src   = (const float*)d_in[2];
    const float* sc_skip  = (const float*)d_in[3];
    const float* pos_src  = (const float*)d_in[4];
    const float* pos_tgt  = (const float*)d_in[5];
    const int*   isrc     = (const int*)d_in[6];
    const float* W1_mv    = (const float*)d_in[8];
    const float* W2_mv    = (const float*)d_in[9];
    const float* W1_s     = (const float*)d_in[10];
    const float* b1_s     = (const float*)d_in[11];
    const float* W2_s     = (const float*)d_in[12];
    const float* b2_s     = (const float*)d_in[13];

    float* out_mv = (float*)d_out;
    float* out_sc = out_mv + (size_t)N_TGT * CCH * MVD;

    prep_all<<<N_SRC / PREP_ROWS, 256>>>(mv_src, sc_src, W1_mv, W2_mv, W1_s, W2_s);
    fused_kernel<<<N_TGT / TGT_PER_BLOCK, TPB>>>(
        mv_skip, sc_skip, pos_src, pos_tgt, isrc,
        b1_s, b2_s, out_mv, out_sc);
}

// round 13
// speedup vs baseline: 1.0523x; 1.0012x over previous
#include <cuda_runtime.h>
#include <cuda_fp16.h>
#include <cstddef>

#define N_SRC   16384
#define N_TGT   65536
#define KNBR    8
#define CCH     16
#define CSKIP   2
#define SSC     32
#define HID     64
#define MVD     16
#define ROW_MV  (CCH*MVD)      // 256
#define TPB     128
#define TGT_PER_BLOCK 16
#define HA_STRIDE 68
#define SK_STRIDE 36
#define PREP_ROWS 16           // source rows per block (1024 blocks)

__device__ __half g_mvTh[(size_t)N_SRC * ROW_MV]; // mv_src @ Weff[0:16]  (8 MB fp16)
__device__ __half g_scTh[(size_t)N_SRC * HID];    // sc_src @ W1a         (2 MB fp16)
__device__ __half g_w1bh[SSC * HID];              // W1_s rows 32..63 fp16
__device__ __half g_w2p[HID * SSC];               // W2 packed: [hc][ch][r] fp16
__device__ float  g_wsk[2 * CCH];                 // Weff rows 16,17

__device__ __forceinline__ float gelu_tanh(float x)
{
    const float c0 = 0.7978845608028654f;
    float u = c0 * fmaf(0.044715f * x, x * x, x);
    float t = tanhf(u);
    return 0.5f * x * (1.0f + t);
}

// ---------------------------------------------------------------------------
// Prep: 1024 blocks x 256 thr, 16 rows each. smem ~13.1 KB -> 7 blocks/SM ->
// single wave. scT batches 8 rows/warp over half2-packed smem weights.
// ---------------------------------------------------------------------------
__global__ __launch_bounds__(256) void prep_all(
    const float* __restrict__ mv_src, const float* __restrict__ sc_src,
    const float* __restrict__ W1_mv,  const float* __restrict__ W2_mv,
    const float* __restrict__ W1_s,   const float* __restrict__ W2_s)
{
    __shared__ __align__(16) float   rows[8 * 256];        // 8 KB (chunk of 8 rows)
    __shared__ __align__(16) float   we[CCH * CCH];        // 1 KB
    __shared__ __align__(16) __half2 w1h[SSC * 32];        // 2 KB  [j][h-pair]
    __shared__ __align__(16) float   xs[PREP_ROWS * 33];   // 2.1 KB

    const int tid  = threadIdx.x;
    const int lane = tid & 31;
    const int warp = tid >> 5;
    const int s0   = blockIdx.x * PREP_ROWS;

    // Weff[cp][c] for cp<16 (warp-uniform-ish __ldg dots, L1 broadcast)
    {
        const int cp = tid >> 4, c = tid & 15;
        float acc = 0.f;
        #pragma unroll
        for (int h = 0; h < HID; h++)
            acc = fmaf(__ldg(W1_mv + cp * HID + h), __ldg(W2_mv + h * CCH + c), acc);
        we[tid] = acc;
    }
    // stage sc rows (512 floats)
    {
        int idx = tid;
        xs[(idx >> 5) * 33 + (idx & 31)] = __ldg(sc_src + (size_t)s0 * SSC + idx);
        idx = tid + 256;
        xs[(idx >> 5) * 33 + (idx & 31)] = __ldg(sc_src + (size_t)s0 * SSC + idx);
    }
    // stage W1a as half2 pairs: w1h[j*32+hp] = (W1[j][2hp], W1[j][2hp+1])
    #pragma unroll
    for (int it = 0; it < 4; it++) {
        const int idx = tid + 256 * it;      // 0..1023
        const int j = idx >> 5, hp = idx & 31;
        float2 wv = __ldg((const float2*)(W1_s + j * HID + 2 * hp));
        w1h[idx] = __floats2half2_rn(wv.x, wv.y);
    }
    // block 0: weight side-products
    if (blockIdx.x == 0) {
        #pragma unroll
        for (int i = 0; i < 8; i++) {
            const int idx = tid + 256 * i;               // 0..2047
            g_w1bh[idx] = __float2half_rn(__ldg(W1_s + SSC * HID + idx));
            const int hc = idx >> 8, ch = (idx >> 3) & 31, r = idx & 7;
            g_w2p[idx] = __float2half_rn(__ldg(W2_s + (hc * 8 + r) * SSC + ch));
        }
        if (tid < 32) {
            const int cp = 16 + (tid >> 4), c = tid & 15;
            float acc = 0.f;
            #pragma unroll
            for (int h = 0; h < HID; h++)
                acc = fmaf(__ldg(W1_mv + cp * HID + h), __ldg(W2_mv + h * CCH + c), acc);
            g_wsk[tid] = acc;
        }
    }
    __syncthreads();

    // ---- mvT fp16: 2 chunks of 8 rows (warp per row; float4 LDS reads) ----
    const int mrow = warp;               // 0..7
    const int c    = lane >> 1;          // output channel
    const int i0   = (lane & 1) * 8;     // blade offset
    #pragma unroll
    for (int ch = 0; ch < 2; ch++) {
        {
            const float4* src = (const float4*)(mv_src + (size_t)(s0 + ch * 8) * 256);
            float4* dst = (float4*)rows;
            dst[tid]       = __ldg(src + tid);
            dst[tid + 256] = __ldg(src + tid + 256);
        }
        __syncthreads();
        {
            const float* row = rows + mrow * 256;
            float acc[8];
            #pragma unroll
            for (int di = 0; di < 8; di++) acc[di] = 0.f;
            #pragma unroll
            for (int cp = 0; cp < 16; cp++) {
                const float wv = we[cp * 16 + c];
                const float4* rp4 = (const float4*)(row + cp * 16 + i0);
                float4 va = rp4[0], vb = rp4[1];
                acc[0] = fmaf(va.x, wv, acc[0]); acc[1] = fmaf(va.y, wv, acc[1]);
                acc[2] = fmaf(va.z, wv, acc[2]); acc[3] = fmaf(va.w, wv, acc[3]);
                acc[4] = fmaf(vb.x, wv, acc[4]); acc[5] = fmaf(vb.y, wv, acc[5]);
                acc[6] = fmaf(vb.z, wv, acc[6]); acc[7] = fmaf(vb.w, wv, acc[7]);
            }
            __half2 h2[4];
            #pragma unroll
            for (int p = 0; p < 4; p++)
                h2[p] = __floats2half2_rn(acc[2 * p], acc[2 * p + 1]);
            *(uint4*)(g_mvTh + (size_t)(s0 + ch * 8 + mrow) * 256 + c * 16 + i0) =
                *(const uint4*)h2;
        }
        __syncthreads();
    }

    // ---- scT fp16: warps 0-1, 8 rows each; lane = h-pair ----
    if (warp < 2) {
        const int rb = warp * 8;
        float a0[8], a1[8];
        #pragma unroll
        for (int r = 0; r < 8; r++) { a0[r] = 0.f; a1[r] = 0.f; }
        #pragma unroll
        for (int j = 0; j < SSC; j++) {
            float2 wf = __half22float2(w1h[j * 32 + lane]);   // 128B/warp = 1 wf
            #pragma unroll
            for (int r = 0; r < 8; r++) {
                const float x = xs[(rb + r) * 33 + j];        // broadcast, 1 wf
                a0[r] = fmaf(x, wf.x, a0[r]);
                a1[r] = fmaf(x, wf.y, a1[r]);
            }
        }
        #pragma unroll
        for (int r = 0; r < 8; r++)
            *(__half2*)(g_scTh + (size_t)(s0 + rb + r) * HID + 2 * lane) =
                __floats2half2_rn(a0[r], a1[r]);
    }
}

// ---------------------------------------------------------------------------
// Warp-private pipeline: warp w owns targets {4w .. 4w+3}.
// Interp-h carried in REGISTERS from phase 1 to phase 3a (no sHA roundtrip).
// ---------------------------------------------------------------------------
__global__ __launch_bounds__(TPB, 6) void fused_kernel(
    const float* __restrict__ mv_skip, const float* __restrict__ sc_skip,
    const float* __restrict__ pos_src, const float* __restrict__ pos_tgt,
    const int*   __restrict__ isrc,
    const float* __restrict__ b1_s,    const float* __restrict__ b2_s,
    float* __restrict__ out_mv,        float* __restrict__ out_sc)
{
    __shared__ __align__(16) float sHA[TGT_PER_BLOCK * HA_STRIDE];
    __shared__ __align__(16) float sSK[TGT_PER_BLOCK * SK_STRIDE];

    const int tid  = threadIdx.x;
    const int lane = tid & 31;
    const int warp = tid >> 5;
    const int tbase = blockIdx.x * TGT_PER_BLOCK;
    const int r0 = warp * 4;

    const int cch = lane >> 1;
    const float w16 = __ldg(g_wsk + cch);
    const float w17 = __ldg(g_wsk + 16 + cch);

    float hh0[4], hh1[4];   // interp hidden, h = (2*lane, 2*lane+1), per target

    // ---------------- Phase 1: IDW gather of fp16 transformed sources -------
    #pragma unroll
    for (int u = 0; u < 4; u++) {
        const int tl = r0 + u;
        const int t  = tbase + tl;

        float wk = 0.f;
        int   sk = 0;
        if (lane < KNBR) {
            sk = isrc[t * KNBR + lane];
            float dx = pos_src[sk * 3 + 0] - pos_tgt[t * 3 + 0];
            float dy = pos_src[sk * 3 + 1] - pos_tgt[t * 3 + 1];
            float dz = pos_src[sk * 3 + 2] - pos_tgt[t * 3 + 2];
            float d2 = fmaf(dx, dx, fmaf(dy, dy, dz * dz));
            d2 = fmaxf(d2, 1e-16f);
            wk = 1.0f / d2;
        }
        float den = wk;
        #pragma unroll
        for (int o = 16; o; o >>= 1) den += __shfl_xor_sync(0xffffffffu, den, o);
        const float invd = 1.0f / den;

        float acc[8];
        #pragma unroll
        for (int j = 0; j < 8; j++) acc[j] = 0.f;
        float h0 = 0.f, h1 = 0.f;

        #pragma unroll
        for (int k = 0; k < KNBR; k++) {
            const float w = __shfl_sync(0xffffffffu, wk, k);
            const int   s = __shfl_sync(0xffffffffu, sk, k);
            uint4 v = __ldg((const uint4*)(g_mvTh + (size_t)s * ROW_MV) + lane);
            const __half2* hv = (const __half2*)&v;
            float2 f0 = __half22float2(hv[0]);
            float2 f1 = __half22float2(hv[1]);
            float2 f2 = __half22float2(hv[2]);
            float2 f3 = __half22float2(hv[3]);
            acc[0] = fmaf(w, f0.x, acc[0]); acc[1] = fmaf(w, f0.y, acc[1]);
            acc[2] = fmaf(w, f1.x, acc[2]); acc[3] = fmaf(w, f1.y, acc[3]);
            acc[4] = fmaf(w, f2.x, acc[4]); acc[5] = fmaf(w, f2.y, acc[5]);
            acc[6] = fmaf(w, f3.x, acc[6]); acc[7] = fmaf(w, f3.y, acc[7]);
            __half2 sv = __ldg((const __half2*)(g_scTh + (size_t)s * HID) + lane);
            float2 sf = __half22float2(sv);
            h0 = fmaf(w, sf.x, h0); h1 = fmaf(w, sf.y, h1);
        }

        const int ib = (lane & 1) * 8;
        float4 s0a = __ldg((const float4*)(mv_skip + (size_t)t * 32 + ib));
        float4 s0b = __ldg((const float4*)(mv_skip + (size_t)t * 32 + ib + 4));
        float4 s1a = __ldg((const float4*)(mv_skip + (size_t)t * 32 + 16 + ib));
        float4 s1b = __ldg((const float4*)(mv_skip + (size_t)t * 32 + 16 + ib + 4));

        float4 o0, o1;
        o0.x = fmaf(acc[0], invd, fmaf(s0a.x, w16, s1a.x * w17));
        o0.y = fmaf(acc[1], invd, fmaf(s0a.y, w16, s1a.y * w17));
        o0.z = fmaf(acc[2], invd, fmaf(s0a.z, w16, s1a.z * w17));
        o0.w = fmaf(acc[3], invd, fmaf(s0a.w, w16, s1a.w * w17));
        o1.x = fmaf(acc[4], invd, fmaf(s0b.x, w16, s1b.x * w17));
        o1.y = fmaf(acc[5], invd, fmaf(s0b.y, w16, s1b.y * w17));
        o1.z = fmaf(acc[6], invd, fmaf(s0b.z, w16, s1b.z * w17));
        o1.w = fmaf(acc[7], invd, fmaf(s0b.w, w16, s1b.w * w17));

        float4* dst = (float4*)(out_mv + (size_t)t * ROW_MV + 8 * lane);
        dst[0] = o0;
        dst[1] = o1;

        hh0[u] = h0 * invd;
        hh1[u] = h1 * invd;
        sSK[tl * SK_STRIDE + lane] = sc_skip[(size_t)t * SSC + lane];
    }
    __syncwarp();

    // ---------------- Phase 3a: hidden = gelu(interp_h + skip@W1b + b1) -----
    {
        float2 bb = __ldg((const float2*)(b1_s + 2 * lane));
        float a0x = bb.x + hh0[0], a0y = bb.y + hh1[0];
        float a1x = bb.x + hh0[1], a1y = bb.y + hh1[1];
        float a2x = bb.x + hh0[2], a2y = bb.y + hh1[2];
        float a3x = bb.x + hh0[3], a3y = bb.y + hh1[3];
        const float* x0 = sSK + (r0 + 0) * SK_STRIDE;
        const float* x1 = sSK + (r0 + 1) * SK_STRIDE;
        const float* x2 = sSK + (r0 + 2) * SK_STRIDE;
        const float* x3 = sSK + (r0 + 3) * SK_STRIDE;
        #pragma unroll
        for (int jc = 0; jc < 8; jc++) {
            float4 v0 = *(const float4*)(x0 + 4 * jc);
            float4 v1 = *(const float4*)(x1 + 4 * jc);
            float4 v2 = *(const float4*)(x2 + 4 * jc);
            float4 v3 = *(const float4*)(x3 + 4 * jc);
            #pragma unroll
            for (int r = 0; r < 4; r++) {
                const int j = 4 * jc + r;
                __half2 wh = __ldg((const __half2*)(g_w1bh + j * HID + 2 * lane));
                float2 wv = __half22float2(wh);
                const float e0 = (r == 0) ? v0.x : (r == 1) ? v0.y : (r == 2) ? v0.z : v0.w;
                const float e1 = (r == 0) ? v1.x : (r == 1) ? v1.y : (r == 2) ? v1.z : v1.w;
                const float e2 = (r == 0) ? v2.x : (r == 1) ? v2.y : (r == 2) ? v2.z : v2.w;
                const float e3 = (r == 0) ? v3.x : (r == 1) ? v3.y : (r == 2) ? v3.z : v3.w;
                a0x = fmaf(e0, wv.x, a0x); a0y = fmaf(e0, wv.y, a0y);
                a1x = fmaf(e1, wv.x, a1x); a1y = fmaf(e1, wv.y, a1y);
                a2x = fmaf(e2, wv.x, a2x); a2y = fmaf(e2, wv.y, a2y);
                a3x = fmaf(e3, wv.x, a3x); a3y = fmaf(e3, wv.y, a3y);
            }
        }
        *(float2*)(sHA + (r0 + 0) * HA_STRIDE + 2 * lane) = make_float2(gelu_tanh(a0x), gelu_tanh(a0y));
        *(float2*)(sHA + (r0 + 1) * HA_STRIDE + 2 * lane) = make_float2(gelu_tanh(a1x), gelu_tanh(a1y));
        *(float2*)(sHA + (r0 + 2) * HA_STRIDE + 2 * lane) = make_float2(gelu_tanh(a2x), gelu_tanh(a2y));
        *(float2*)(sHA + (r0 + 3) * HA_STRIDE + 2 * lane) = make_float2(gelu_tanh(a3x), gelu_tanh(a3y));
    }
    __syncwarp();

    // ---------------- Phase 3b: scalar output (lane = channel, packed fp16 W2)
    {
        const float bb = __ldg(b2_s + lane);
        float a0 = bb, a1 = bb, a2 = bb, a3 = bb;
        const float* h0 = sHA + (r0 + 0) * HA_STRIDE;
        const float* h1 = sHA + (r0 + 1) * HA_STRIDE;
        const float* h2 = sHA + (r0 + 2) * HA_STRIDE;
        const float* h3 = sHA + (r0 + 3) * HA_STRIDE;
        #pragma unroll
        for (int hc = 0; hc < 8; hc++) {
            uint4 wv = __ldg((const uint4*)(g_w2p + hc * 256 + lane * 8));
            const __half2* wh = (const __half2*)&wv;
            float2 wf0 = __half22float2(wh[0]);
            float2 wf1 = __half22float2(wh[1]);
            float2 wf2 = __half22float2(wh[2]);
            float2 wf3 = __half22float2(wh[3]);
            float4 va0 = *(const float4*)(h0 + 8 * hc);
            float4 vb0 = *(const float4*)(h0 + 8 * hc + 4);
            float4 va1 = *(const float4*)(h1 + 8 * hc);
            float4 vb1 = *(const float4*)(h1 + 8 * hc + 4);
            float4 va2 = *(const float4*)(h2 + 8 * hc);
            float4 vb2 = *(const float4*)(h2 + 8 * hc + 4);
            float4 va3 = *(const float4*)(h3 + 8 * hc);
            float4 vb3 = *(const float4*)(h3 + 8 * hc + 4);
            a0 = fmaf(va0.x, wf0.x, a0); a0 = fmaf(va0.y, wf0.y, a0);
            a0 = fmaf(va0.z, wf1.x, a0); a0 = fmaf(va0.w, wf1.y, a0);
            a0 = fmaf(vb0.x, wf2.x, a0); a0 = fmaf(vb0.y, wf2.y, a0);
            a0 = fmaf(vb0.z, wf3.x, a0); a0 = fmaf(vb0.w, wf3.y, a0);
            a1 = fmaf(va1.x, wf0.x, a1); a1 = fmaf(va1.y, wf0.y, a1);
            a1 = fmaf(va1.z, wf1.x, a1); a1 = fmaf(va1.w, wf1.y, a1);
            a1 = fmaf(vb1.x, wf2.x, a1); a1 = fmaf(vb1.y, wf2.y, a1);
            a1 = fmaf(vb1.z, wf3.x, a1); a1 = fmaf(vb1.w, wf3.y, a1);
            a2 = fmaf(va2.x, wf0.x, a2); a2 = fmaf(va2.y, wf0.y, a2);
            a2 = fmaf(va2.z, wf1.x, a2); a2 = fmaf(va2.w, wf1.y, a2);
            a2 = fmaf(vb2.x, wf2.x, a2); a2 = fmaf(vb2.y, wf2.y, a2);
            a2 = fmaf(vb2.z, wf3.x, a2); a2 = fmaf(vb2.w, wf3.y, a2);
            a3 = fmaf(va3.x, wf0.x, a3); a3 = fmaf(va3.y, wf0.y, a3);
            a3 = fmaf(va3.z, wf1.x, a3); a3 = fmaf(va3.w, wf1.y, a3);
            a3 = fmaf(vb3.x, wf2.x, a3); a3 = fmaf(vb3.y, wf2.y, a3);
            a3 = fmaf(vb3.z, wf3.x, a3); a3 = fmaf(vb3.w, wf3.y, a3);
        }
        out_sc[(size_t)(tbase + r0 + 0) * SSC + lane] = a0;
        out_sc[(size_t)(tbase + r0 + 1) * SSC + lane] = a1;
        out_sc[(size_t)(tbase + r0 + 2) * SSC + lane] = a2;
        out_sc[(size_t)(tbase + r0 + 3) * SSC + lane] = a3;
    }
}

// ---------------------------------------------------------------------------
extern "C" void kernel_launch(void* const* d_in, const int* in_sizes, int n_in,
                              void* d_out, int out_size)
{
    const float* mv_src   = (const float*)d_in[0];
    const float* mv_skip  = (const float*)d_in[1];
    const float* sc_src   = (const float*)d_in[2];
    const float* sc_skip  = (const float*)d_in[3];
    const float* pos_src  = (const float*)d_in[4];
    const float* pos_tgt  = (const float*)d_in[5];
    const int*   isrc     = (const int*)d_in[6];
    const float* W1_mv    = (const float*)d_in[8];
    const float* W2_mv    = (const float*)d_in[9];
    const float* W1_s     = (const float*)d_in[10];
    const float* b1_s     = (const float*)d_in[11];
    const float* W2_s     = (const float*)d_in[12];
    const float* b2_s     = (const float*)d_in[13];

    float* out_mv = (float*)d_out;
    float* out_sc = out_mv + (size_t)N_TGT * CCH * MVD;

    prep_all<<<N_SRC / PREP_ROWS, 256>>>(mv_src, sc_src, W1_mv, W2_mv, W1_s, W2_s);
    fused_kernel<<<N_TGT / TGT_PER_BLOCK, TPB>>>(
        mv_skip, sc_skip, pos_src, pos_tgt, isrc,
        b1_s, b2_s, out_mv, out_sc);
}